// round 14
// baseline (speedup 1.0000x reference)
#include <cuda_runtime.h>
#include <cuda_fp16.h>
#include <mma.h>
#include <math.h>

using namespace nvcuda;

// ---------------- scratch (device globals; no allocation at launch) ----------------
#define NMAX 10000
#define NP   10048            // NMAX padded to multiple of 64 (guard-free wmma)
#define EMAX 320000
#define ETMAX (EMAX + NMAX)
#define NB_TOT (NP / 64)      // 157 row blocks
#define NB_A   79             // first-half row blocks
#define NSPLIT (NB_A * 64)    // 5056 node split

__device__ __half g_hhA[NP * 768];    // GEMM out, layers 1 (256 used) & 3 (768)
__device__ __half g_hhB[NP * 256];    // GEMM out, layer 2
__device__ __half g_x1h[NP * 256];    // layer outputs, fp16 only
__device__ __half g_x2h[NP * 256];
__device__ __half g_x3h[NP * 768];
__device__ __half g_w2h[256 * 256];   // fp16 weights
__device__ __half g_w3h[256 * 768];
__device__ float g_al [NMAX * 12];
__device__ float g_ar [NMAX * 12];
__device__ float g_e  [12 * ETMAX];   // HEAD-MAJOR: g_e[h*ETMAX + slot] = exp(leaky(score))
__device__ float g_px [NMAX * 128];
__device__ float g_wl1[8 * 16],  g_wr1[8 * 16];     // TRANSPOSED: [h][k]
__device__ float g_wl2[8 * 256], g_wr2[8 * 256];
__device__ float g_wl3[12 * 256], g_wr3[12 * 256];
__device__ int   g_deg   [NMAX];
__device__ int   g_rowptr[NMAX + 1];
__device__ int   g_cursor[NMAX];
__device__ int   g_csrsrc[ETMAX];
__device__ int   g_csrdst[ETMAX];

__device__ __forceinline__ float sigmoidf_(float x) {
    return 1.f / (1.f + expf(-x));
}

static inline int cdiv(int a, int b) { return (a + b - 1) / b; }

// ---------------- CSR build ----------------
__global__ void count_deg(const int* __restrict__ ei, int E, int Et, int* __restrict__ deg) {
    int e = blockIdx.x * blockDim.x + threadIdx.x;
    if (e >= Et) return;
    int d = (e < E) ? ei[E + e] : (e - E);
    atomicAdd(&deg[d], 1);
}

__global__ void scan_deg(const int* __restrict__ deg, int* __restrict__ rowptr,
                         int* __restrict__ cursor, int Nn) {
    __shared__ int part[256];
    __shared__ int partx[256];
    int chunk = (Nn + 255) / 256;
    int begin = threadIdx.x * chunk;
    int end = begin + chunk; if (end > Nn) end = Nn;
    if (begin > Nn) begin = Nn;
    int s = 0;
    for (int i = begin; i < end; ++i) s += deg[i];
    part[threadIdx.x] = s;
    __syncthreads();
    if (threadIdx.x == 0) {
        int run = 0;
        for (int i = 0; i < 256; ++i) { partx[i] = run; run += part[i]; }
    }
    __syncthreads();
    int run = partx[threadIdx.x];
    for (int i = begin; i < end; ++i) {
        rowptr[i] = run; cursor[i] = run;
        run += deg[i];
    }
    if (end == Nn && begin <= Nn) rowptr[Nn] = run;
}

__global__ void scatter_csr(const int* __restrict__ ei, int E, int Et,
                            int* __restrict__ cursor, int* __restrict__ csr_src,
                            int* __restrict__ csr_dst) {
    int e = blockIdx.x * blockDim.x + threadIdx.x;
    if (e >= Et) return;
    int s, d;
    if (e < E) { s = ei[e]; d = ei[E + e]; }
    else       { s = e - E; d = e - E; }
    int pos = atomicAdd(&cursor[d], 1);
    csr_src[pos] = s;
    csr_dst[pos] = d;
}

// ---------------- fold all attention vectors (one launch, TRANSPOSED output) ----------------
__global__ void wa_all(const float* __restrict__ W1, const float* __restrict__ a1s, const float* __restrict__ a1d,
                       const float* __restrict__ W2, const float* __restrict__ a2s, const float* __restrict__ a2d,
                       const float* __restrict__ W3, const float* __restrict__ a3s, const float* __restrict__ a3d,
                       float* __restrict__ wl1, float* __restrict__ wr1,
                       float* __restrict__ wl2, float* __restrict__ wr2,
                       float* __restrict__ wl3, float* __restrict__ wr3) {
    int t = blockIdx.x * blockDim.x + threadIdx.x;
    const float *W, *as, *ad; float *wl, *wr;
    int K, H, C, idx;
    if (t < 128)              { idx = t;        K = 16;  H = 8;  C = 32; W = W1; as = a1s; ad = a1d; wl = wl1; wr = wr1; }
    else if (t < 128 + 2048)  { idx = t - 128;  K = 256; H = 8;  C = 32; W = W2; as = a2s; ad = a2d; wl = wl2; wr = wr2; }
    else if (t < 128 + 2048 + 3072) { idx = t - 2176; K = 256; H = 12; C = 64; W = W3; as = a3s; ad = a3d; wl = wl3; wr = wr3; }
    else return;
    int k = idx / H, h = idx - k * H;
    const float* wrow = W + (size_t)k * H * C + h * C;
    float sl = 0.f, sr = 0.f;
    for (int c = 0; c < C; ++c) {
        float w = wrow[c];
        sl += w * as[h * C + c];
        sr += w * ad[h * C + c];
    }
    wl[h * K + k] = sl;      // transposed
    wr[h * K + k] = sr;
}

// ---------------- fp32 -> fp16 weight conversion (both weights, one launch) ----------------
__global__ void f2h_both(const float* __restrict__ W2, const float* __restrict__ W3,
                         __half* __restrict__ w2h, __half* __restrict__ w3h) {
    int t = blockIdx.x * blockDim.x + threadIdx.x;
    if (t < 256 * 256) w2h[t] = __float2half_rn(W2[t]);
    int u = t - 256 * 256;
    if (u >= 0 && u < 256 * 768) w3h[u] = __float2half_rn(W3[u]);
}

// ---------------- layer-1 SGEMM (K=16, fp32 in, fp16 out) ----------------
__global__ void sgemm64h(const float* __restrict__ A, const float* __restrict__ B,
                         __half* __restrict__ Cmat, int M, int N, int K) {
    __shared__ float As[16][68];
    __shared__ float Bs[16][64];
    int t = threadIdx.x;
    int row0 = blockIdx.x * 64;
    int col0 = blockIdx.y * 64;
    int tx = t & 15, ty = t >> 4;
    int ar = t >> 2, ac = (t & 3) * 4;
    int br = t >> 4, bc = (t & 15) * 4;
    float acc[4][4];
#pragma unroll
    for (int i = 0; i < 4; ++i)
#pragma unroll
        for (int j = 0; j < 4; ++j) acc[i][j] = 0.f;

    for (int k0 = 0; k0 < K; k0 += 16) {
        float4 av = make_float4(0.f, 0.f, 0.f, 0.f);
        if (row0 + ar < M)
            av = *(const float4*)(A + (size_t)(row0 + ar) * K + k0 + ac);
        As[ac + 0][ar] = av.x;
        As[ac + 1][ar] = av.y;
        As[ac + 2][ar] = av.z;
        As[ac + 3][ar] = av.w;
        *(float4*)&Bs[br][bc] = *(const float4*)(B + (size_t)(k0 + br) * N + col0 + bc);
        __syncthreads();
#pragma unroll
        for (int k = 0; k < 16; ++k) {
            float4 a4 = *(const float4*)&As[k][ty * 4];
            float4 b4 = *(const float4*)&Bs[k][tx * 4];
            acc[0][0] += a4.x * b4.x; acc[0][1] += a4.x * b4.y;
            acc[0][2] += a4.x * b4.z; acc[0][3] += a4.x * b4.w;
            acc[1][0] += a4.y * b4.x; acc[1][1] += a4.y * b4.y;
            acc[1][2] += a4.y * b4.z; acc[1][3] += a4.y * b4.w;
            acc[2][0] += a4.z * b4.x; acc[2][1] += a4.z * b4.y;
            acc[2][2] += a4.z * b4.z; acc[2][3] += a4.z * b4.w;
            acc[3][0] += a4.w * b4.x; acc[3][1] += a4.w * b4.y;
            acc[3][2] += a4.w * b4.z; acc[3][3] += a4.w * b4.w;
        }
        __syncthreads();
    }
#pragma unroll
    for (int i = 0; i < 4; ++i) {
        int r = row0 + ty * 4 + i;
        if (r < M) {
            __half2 p0 = __halves2half2(__float2half_rn(acc[i][0]), __float2half_rn(acc[i][1]));
            __half2 p1 = __halves2half2(__float2half_rn(acc[i][2]), __float2half_rn(acc[i][3]));
            __half2* cp = (__half2*)(Cmat + (size_t)r * N + col0 + tx * 4);
            cp[0] = p0;
            cp[1] = p1;
        }
    }
}

// ---------------- HMMA GEMM with row-block offset ----------------
__global__ void hgemm64(const __half* __restrict__ A, const __half* __restrict__ B,
                        __half* __restrict__ Cmat, int N, int K, int rb0) {
    __shared__ __half As[64][24];
    __shared__ __half Bs[16][72];
    __shared__ float Cs[8][512];
    int t = threadIdx.x;
    int warp = t >> 5, lane = t & 31;
    int row0 = (blockIdx.x + rb0) * 64, col0 = blockIdx.y * 64;
    int wr = warp & 3;
    int wc = warp >> 2;

    wmma::fragment<wmma::accumulator, 16, 16, 16, float> acc0, acc1;
    wmma::fill_fragment(acc0, 0.f);
    wmma::fill_fragment(acc1, 0.f);

    int arow = t >> 2, acol = (t & 3) * 4;
    int brow = t >> 4, bcol = (t & 15) * 4;

    for (int k0 = 0; k0 < K; k0 += 16) {
        *(uint2*)&As[arow][acol] = *(const uint2*)(A + (size_t)(row0 + arow) * K + k0 + acol);
        *(uint2*)&Bs[brow][bcol] = *(const uint2*)(B + (size_t)(k0 + brow) * N + col0 + bcol);
        __syncthreads();
        wmma::fragment<wmma::matrix_a, 16, 16, 16, __half, wmma::row_major> af;
        wmma::fragment<wmma::matrix_b, 16, 16, 16, __half, wmma::row_major> bf;
        wmma::load_matrix_sync(af, &As[wr * 16][0], 24);
        wmma::load_matrix_sync(bf, &Bs[0][wc * 32], 72);
        wmma::mma_sync(acc0, af, bf, acc0);
        wmma::load_matrix_sync(bf, &Bs[0][wc * 32 + 16], 72);
        wmma::mma_sync(acc1, af, bf, acc1);
        __syncthreads();
    }
    wmma::store_matrix_sync(&Cs[warp][0],  acc0, 32, wmma::mem_row_major);
    wmma::store_matrix_sync(&Cs[warp][16], acc1, 32, wmma::mem_row_major);
    __syncwarp();
    for (int i = lane; i < 512; i += 32) {
        int r = i >> 5, c = i & 31;
        Cmat[(size_t)(row0 + wr * 16 + r) * N + col0 + wc * 32 + c] =
            __float2half_rn(Cs[warp][r * 32 + c]);
    }
}

// ---------------- layer-1 al/ar from fp32 X (transposed w) ----------------
__global__ void alar_x(const float* __restrict__ X,
                       const float* __restrict__ wlt, const float* __restrict__ wrt,
                       float* __restrict__ al, float* __restrict__ ar,
                       int Nn, int K, int H) {
    int t = blockIdx.x * blockDim.x + threadIdx.x;
    if (t >= Nn * H) return;
    int n = t / H, h = t - n * H;
    const float* xr = X + (size_t)n * K;
    const float* wl = wlt + h * K;
    const float* wr = wrt + h * K;
    float sa = 0.f, sd = 0.f;
    for (int k = 0; k < K; ++k) {
        float xv = xr[k];
        sa += xv * wl[k];
        sd += xv * wr[k];
    }
    al[t] = sa;
    ar[t] = sd;
}

// ---------------- layers 2/3 al/ar: warp per node, fp16 X, transposed w (K=256) ----------------
__global__ void alar_wxh(const __half* __restrict__ X,
                         const float* __restrict__ wlt, const float* __restrict__ wrt,
                         float* __restrict__ al, float* __restrict__ ar,
                         int Nn, int H) {
    const int K = 256;
    int gw = (blockIdx.x * blockDim.x + threadIdx.x) >> 5;
    int lane = threadIdx.x & 31;
    if (gw >= Nn) return;
    // each lane holds 8 contiguous x values
    float xv[8];
    const __half2* xr = (const __half2*)(X + (size_t)gw * K) + lane * 4;
#pragma unroll
    for (int i = 0; i < 4; ++i) {
        float2 f = __half22float2(xr[i]);
        xv[2 * i] = f.x; xv[2 * i + 1] = f.y;
    }
    for (int h = 0; h < H; ++h) {
        const float4* wl4 = (const float4*)(wlt + h * K + lane * 8);
        const float4* wr4 = (const float4*)(wrt + h * K + lane * 8);
        float4 la = wl4[0], lb = wl4[1];
        float4 ra = wr4[0], rb = wr4[1];
        float sa = xv[0]*la.x + xv[1]*la.y + xv[2]*la.z + xv[3]*la.w
                 + xv[4]*lb.x + xv[5]*lb.y + xv[6]*lb.z + xv[7]*lb.w;
        float sd = xv[0]*ra.x + xv[1]*ra.y + xv[2]*ra.z + xv[3]*ra.w
                 + xv[4]*rb.x + xv[5]*rb.y + xv[6]*rb.z + xv[7]*rb.w;
#pragma unroll
        for (int o = 16; o; o >>= 1) {
            sa += __shfl_xor_sync(0xffffffffu, sa, o);
            sd += __shfl_xor_sync(0xffffffffu, sd, o);
        }
        if (lane == 0) {
            al[gw * H + h] = sa;
            ar[gw * H + h] = sd;
        }
    }
}

// ---------------- per-slot exp(leaky(score)) (CSR order, HEAD-MAJOR) ----------------
template<int H>
__global__ void edge_score_csr(const int* __restrict__ csr_src, const int* __restrict__ csr_dst,
                               int Et,
                               const float* __restrict__ al, const float* __restrict__ ar,
                               float* __restrict__ ebuf) {
    int i = blockIdx.x * blockDim.x + threadIdx.x;
    if (i >= Et) return;
    int s = csr_src[i];
    int d = csr_dst[i];
    const float4* a4 = (const float4*)(al + s * H);
    const float4* r4 = (const float4*)(ar + d * H);
#pragma unroll
    for (int q = 0; q < H / 4; ++q) {
        float4 a = a4[q], r = r4[q];
        float v0 = a.x + r.x; v0 = v0 > 0.f ? v0 : 0.2f * v0;
        float v1 = a.y + r.y; v1 = v1 > 0.f ? v1 : 0.2f * v1;
        float v2 = a.z + r.z; v2 = v2 > 0.f ? v2 : 0.2f * v2;
        float v3 = a.w + r.w; v3 = v3 > 0.f ? v3 : 0.2f * v3;
        ebuf[(size_t)(q * 4 + 0) * ETMAX + i] = __expf(v0);
        ebuf[(size_t)(q * 4 + 1) * ETMAX + i] = __expf(v1);
        ebuf[(size_t)(q * 4 + 2) * ETMAX + i] = __expf(v2);
        ebuf[(size_t)(q * 4 + 3) * ETMAX + i] = __expf(v3);
    }
}

// ---------------- agg (H=8, C=32): 4 warps, 2 heads/warp; node range [n0, n0+grid) ----------------
__global__ void agg_h8(const int* __restrict__ rowptr, const int* __restrict__ csr_src,
                       const float* __restrict__ ebuf, const __half* __restrict__ Hmat,
                       const float* __restrict__ bias, __half* __restrict__ Outh, int n0) {
    __shared__ int ssrc[128];
    int n = blockIdx.x + n0;
    int t = threadIdx.x;
    int w = t >> 5, lane = t & 31;
    int rs = rowptr[n], re = rowptr[n + 1];
    const float* ep0 = ebuf + (size_t)(2 * w)     * ETMAX;
    const float* ep1 = ebuf + (size_t)(2 * w + 1) * ETMAX;
    bool hi = lane >= 16;

    float ssum = 0.f, acc0 = 0.f, acc1 = 0.f;
    for (int base = rs; base < re; base += 128) {
        int cnt = re - base; if (cnt > 128) cnt = 128;
        __syncthreads();
        if (t < cnt) ssrc[t] = csr_src[base + t];
        __syncthreads();
#pragma unroll 4
        for (int j = 0; j < cnt; ++j) {
            int s = ssrc[j];
            float a = hi ? ep1[base + j] : ep0[base + j];
            ssum += a;
            const __half2* hp = (const __half2*)(Hmat + (size_t)s * 256 + w * 64);
            float2 vf = __half22float2(hp[lane]);
            acc0 += a * vf.x;
            acc1 += a * vf.y;
        }
    }
    float inv_s = 1.f / ssum;
    int c = w * 64 + lane * 2;
    float v0 = acc0 * inv_s + bias[c];
    float v1 = acc1 * inv_s + bias[c + 1];
    v0 = v0 > 0.f ? v0 : 0.f;
    v1 = v1 > 0.f ? v1 : 0.f;
    *((__half2*)(Outh + (size_t)n * 256 + c)) = __floats2half2_rn(v0, v1);
}

// ---------------- agg (H=12, C=64): 6 warps, 2 heads/warp, uint2 gathers ----------------
__global__ void agg_h12(const int* __restrict__ rowptr, const int* __restrict__ csr_src,
                        const float* __restrict__ ebuf, const __half* __restrict__ Hmat,
                        const float* __restrict__ bias, __half* __restrict__ Outh, int Nn) {
    __shared__ int ssrc[192];
    int n = blockIdx.x;
    int t = threadIdx.x;
    int w = t >> 5, lane = t & 31;
    int rs = rowptr[n], re = rowptr[n + 1];
    const float* ep0 = ebuf + (size_t)(2 * w)     * ETMAX;
    const float* ep1 = ebuf + (size_t)(2 * w + 1) * ETMAX;
    bool hi = lane >= 16;

    float ssum = 0.f, acc0 = 0.f, acc1 = 0.f, acc2 = 0.f, acc3 = 0.f;
    for (int base = rs; base < re; base += 192) {
        int cnt = re - base; if (cnt > 192) cnt = 192;
        __syncthreads();
        if (t < cnt) ssrc[t] = csr_src[base + t];
        __syncthreads();
#pragma unroll 4
        for (int j = 0; j < cnt; ++j) {
            int s = ssrc[j];
            float a = hi ? ep1[base + j] : ep0[base + j];
            ssum += a;
            const uint2* hp = (const uint2*)(Hmat + (size_t)s * 768 + w * 128);
            uint2 u = hp[lane];
            float2 f01 = __half22float2(*(__half2*)&u.x);
            float2 f23 = __half22float2(*(__half2*)&u.y);
            acc0 += a * f01.x;
            acc1 += a * f01.y;
            acc2 += a * f23.x;
            acc3 += a * f23.y;
        }
    }
    float inv_s = 1.f / ssum;
    int c = w * 128 + lane * 4;
    float v0 = acc0 * inv_s + bias[c];
    float v1 = acc1 * inv_s + bias[c + 1];
    float v2 = acc2 * inv_s + bias[c + 2];
    float v3 = acc3 * inv_s + bias[c + 3];
    v0 = v0 > 0.f ? v0 : 0.f;
    v1 = v1 > 0.f ? v1 : 0.f;
    v2 = v2 > 0.f ? v2 : 0.f;
    v3 = v3 > 0.f ? v3 : 0.f;
    __half2* op = (__half2*)(Outh + (size_t)n * 768 + c);
    op[0] = __floats2half2_rn(v0, v1);
    op[1] = __floats2half2_rn(v2, v3);
}

// ---------------- fused tail (fp16 activations in) ----------------
__global__ void tail_fused(const __half* __restrict__ x1, const __half* __restrict__ x2,
                           const __half* __restrict__ x3, const float* __restrict__ Wf,
                           const float* __restrict__ bf, const float* __restrict__ px,
                           const float* __restrict__ M1w,
                           const float* __restrict__ M2w, const float* __restrict__ M2b,
                           const float* __restrict__ M3w, const float* __restrict__ M3b,
                           float* __restrict__ out1, float* __restrict__ out2, int Nn) {
    __shared__ float red[4];
    __shared__ float h1s[128];
    __shared__ float h2s[64];
    __shared__ float o1s;
    int n = blockIdx.x;
    int t = threadIdx.x;
    int lane = t & 31, w = t >> 5;

    float acc = 0.f;
    const __half* p1 = x1 + (size_t)n * 256;
    const __half* p2 = x2 + (size_t)n * 256;
    const __half* p3 = x3 + (size_t)n * 768;
    for (int j = t; j < 256; j += 128) acc += __half2float(p1[j]) * Wf[j];
    for (int j = t; j < 256; j += 128) acc += __half2float(p2[j]) * Wf[256 + j];
    for (int j = t; j < 768; j += 128) acc += __half2float(p3[j]) * Wf[512 + j];
#pragma unroll
    for (int o = 16; o; o >>= 1) acc += __shfl_xor_sync(0xffffffffu, acc, o);
    if (lane == 0) red[w] = acc;
    __syncthreads();
    if (t == 0) {
        float s = red[0] + red[1] + red[2] + red[3];
        float o1 = sigmoidf_(s + bf[0]);
        o1s = o1;
        out1[n] = o1;
    }
    __syncthreads();
    float o1 = o1s;

    float hv = px[(size_t)n * 128 + t] + o1 * M1w[16 * 128 + t];
    h1s[t] = hv > 0.f ? hv : 0.f;
    __syncthreads();

    if (t < 64) {
        float a = M2b[t];
#pragma unroll 8
        for (int k = 0; k < 128; ++k) a += h1s[k] * M2w[k * 64 + t];
        h2s[t] = a > 0.f ? a : 0.f;
    }
    __syncthreads();

    if (w == 0) {
        float a = h2s[lane] * M3w[lane] + h2s[lane + 32] * M3w[lane + 32];
#pragma unroll
        for (int o = 16; o; o >>= 1) a += __shfl_down_sync(0xffffffffu, a, o);
        if (lane == 0) out2[n] = sigmoidf_(a + M3b[0]);
    }
}

// ---------------- mlp1 x-part precompute (overlapped) ----------------
__global__ void mlp1_pre(const float* __restrict__ x,
                         const float* __restrict__ M1w, const float* __restrict__ M1b,
                         float* __restrict__ px, int Nn) {
    int t = blockIdx.x * blockDim.x + threadIdx.x;
    if (t >= Nn * 128) return;
    int n = t / 128, j = t - n * 128;
    float acc = M1b[j];
    const float* xr = x + n * 16;
#pragma unroll
    for (int k = 0; k < 16; ++k) acc += xr[k] * M1w[k * 128 + j];
    px[t] = acc;
}

extern "C" void kernel_launch(void* const* d_in, const int* in_sizes, int n_in,
                              void* d_out, int out_size) {
    const float* x   = (const float*)d_in[0];
    const int*   ei  = (const int*)  d_in[1];
    const float* W1  = (const float*)d_in[3];
    const float* a1s = (const float*)d_in[4];
    const float* a1d = (const float*)d_in[5];
    const float* b1  = (const float*)d_in[6];
    const float* W2  = (const float*)d_in[7];
    const float* a2s = (const float*)d_in[8];
    const float* a2d = (const float*)d_in[9];
    const float* b2  = (const float*)d_in[10];
    const float* W3  = (const float*)d_in[11];
    const float* a3s = (const float*)d_in[12];
    const float* a3d = (const float*)d_in[13];
    const float* b3  = (const float*)d_in[14];
    const float* Wf  = (const float*)d_in[15];
    const float* bf  = (const float*)d_in[16];
    const float* M1w = (const float*)d_in[17];
    const float* M1b = (const float*)d_in[18];
    const float* M2w = (const float*)d_in[19];
    const float* M2b = (const float*)d_in[20];
    const float* M3w = (const float*)d_in[21];
    const float* M3b = (const float*)d_in[22];

    int Nn = in_sizes[0] / 16;
    int E  = in_sizes[1] / 2;
    int Et = E + Nn;
    int nsplit = NSPLIT < Nn ? NSPLIT : Nn;

    __half *hhA_, *hhB_, *x1h_, *x2h_, *x3h_, *w2h_, *w3h_;
    float *al_, *ar_, *e_, *px_;
    float *wl1_, *wr1_, *wl2_, *wr2_, *wl3_, *wr3_;
    int *deg_, *rowptr_, *cursor_, *csrsrc_, *csrdst_;
    cudaGetSymbolAddress((void**)&hhA_,   g_hhA);
    cudaGetSymbolAddress((void**)&hhB_,   g_hhB);
    cudaGetSymbolAddress((void**)&x1h_,   g_x1h);
    cudaGetSymbolAddress((void**)&x2h_,   g_x2h);
    cudaGetSymbolAddress((void**)&x3h_,   g_x3h);
    cudaGetSymbolAddress((void**)&w2h_,   g_w2h);
    cudaGetSymbolAddress((void**)&w3h_,   g_w3h);
    cudaGetSymbolAddress((void**)&al_,    g_al);
    cudaGetSymbolAddress((void**)&ar_,    g_ar);
    cudaGetSymbolAddress((void**)&e_,     g_e);
    cudaGetSymbolAddress((void**)&px_,    g_px);
    cudaGetSymbolAddress((void**)&wl1_,   g_wl1);
    cudaGetSymbolAddress((void**)&wr1_,   g_wr1);
    cudaGetSymbolAddress((void**)&wl2_,   g_wl2);
    cudaGetSymbolAddress((void**)&wr2_,   g_wr2);
    cudaGetSymbolAddress((void**)&wl3_,   g_wl3);
    cudaGetSymbolAddress((void**)&wr3_,   g_wr3);
    cudaGetSymbolAddress((void**)&deg_,   g_deg);
    cudaGetSymbolAddress((void**)&rowptr_,g_rowptr);
    cudaGetSymbolAddress((void**)&cursor_,g_cursor);
    cudaGetSymbolAddress((void**)&csrsrc_,g_csrsrc);
    cudaGetSymbolAddress((void**)&csrdst_,g_csrdst);

    float* out1 = (float*)d_out;
    float* out2 = (float*)d_out + Nn;

    static cudaStream_t s1 = nullptr, s2 = nullptr;
    static cudaEvent_t evF[3], evJ[3], evW, evA[2], evG[2];
    if (!s1) {
        cudaStreamCreateWithFlags(&s1, cudaStreamNonBlocking);
        cudaStreamCreateWithFlags(&s2, cudaStreamNonBlocking);
        for (int i = 0; i < 3; ++i) {
            cudaEventCreateWithFlags(&evF[i], cudaEventDisableTiming);
            cudaEventCreateWithFlags(&evJ[i], cudaEventDisableTiming);
        }
        cudaEventCreateWithFlags(&evW, cudaEventDisableTiming);
        for (int i = 0; i < 2; ++i) {
            cudaEventCreateWithFlags(&evA[i], cudaEventDisableTiming);
            cudaEventCreateWithFlags(&evG[i], cudaEventDisableTiming);
        }
    }
    cudaStream_t s0 = 0;

    // ================= layer 1: fork =================
    cudaEventRecord(evF[0], s0);
    cudaStreamWaitEvent(s1, evF[0], 0);
    // side chain: weight prep + CSR + layer-1 scores + mlp1 precompute
    wa_all<<<cdiv(5248, 128), 128, 0, s1>>>(W1, a1s, a1d, W2, a2s, a2d, W3, a3s, a3d,
                                            wl1_, wr1_, wl2_, wr2_, wl3_, wr3_);
    cudaMemsetAsync(deg_, 0, Nn * sizeof(int), s1);
    count_deg<<<cdiv(Et, 256), 256, 0, s1>>>(ei, E, Et, deg_);
    scan_deg<<<1, 256, 0, s1>>>(deg_, rowptr_, cursor_, Nn);
    scatter_csr<<<cdiv(Et, 256), 256, 0, s1>>>(ei, E, Et, cursor_, csrsrc_, csrdst_);
    alar_x<<<cdiv(Nn * 8, 256), 256, 0, s1>>>(x, wl1_, wr1_, al_, ar_, Nn, 16, 8);
    edge_score_csr<8><<<cdiv(Et, 256), 256, 0, s1>>>(csrsrc_, csrdst_, Et, al_, ar_, e_);
    mlp1_pre<<<cdiv(Nn * 128, 256), 256, 0, s1>>>(x, M1w, M1b, px_, Nn);
    cudaEventRecord(evJ[0], s1);
    f2h_both<<<cdiv(256 * 1024, 256), 256, 0, s1>>>(W2, W3, w2h_, w3h_);
    cudaEventRecord(evW, s1);
    // main: GEMM1 -> hhA
    {
        dim3 gg(cdiv(Nn, 64), 256 / 64);
        sgemm64h<<<gg, 256, 0, s0>>>(x, W1, hhA_, Nn, 256, 16);
    }
    cudaStreamWaitEvent(s0, evJ[0], 0);
    // agg1 split: first half enables hgemm2_a on s2
    agg_h8<<<nsplit, 128, 0, s0>>>(rowptr_, csrsrc_, e_, hhA_, b1, x1h_, 0);
    cudaEventRecord(evA[0], s0);
    agg_h8<<<Nn - nsplit, 128, 0, s0>>>(rowptr_, csrsrc_, e_, hhA_, b1, x1h_, nsplit);
    cudaEventRecord(evF[1], s0);

    // s2: hgemm2 first half (rows [0, NB_A*64)) -> hhB
    cudaStreamWaitEvent(s2, evA[0], 0);
    cudaStreamWaitEvent(s2, evW, 0);
    {
        dim3 gg(NB_A, 256 / 64);
        hgemm64<<<gg, 256, 0, s2>>>(x1h_, w2h_, hhB_, 256, 256, 0);
    }
    cudaEventRecord(evG[0], s2);

    // ================= layer 2 =================
    cudaStreamWaitEvent(s1, evF[1], 0);
    alar_wxh<<<cdiv(Nn * 32, 256), 256, 0, s1>>>(x1h_, wl2_, wr2_, al_, ar_, Nn, 8);
    edge_score_csr<8><<<cdiv(Et, 256), 256, 0, s1>>>(csrsrc_, csrdst_, Et, al_, ar_, e_);
    cudaEventRecord(evJ[1], s1);
    // s0: hgemm2 second half
    cudaStreamWaitEvent(s0, evG[0], 0);
    {
        dim3 gg(NB_TOT - NB_A, 256 / 64);
        hgemm64<<<gg, 256, 0, s0>>>(x1h_, w2h_, hhB_, 256, 256, NB_A);
    }
    cudaStreamWaitEvent(s0, evJ[1], 0);
    agg_h8<<<nsplit, 128, 0, s0>>>(rowptr_, csrsrc_, e_, hhB_, b2, x2h_, 0);
    cudaEventRecord(evA[1], s0);
    agg_h8<<<Nn - nsplit, 128, 0, s0>>>(rowptr_, csrsrc_, e_, hhB_, b2, x2h_, nsplit);
    cudaEventRecord(evF[2], s0);

    // s2: hgemm3 first half -> hhA
    cudaStreamWaitEvent(s2, evA[1], 0);
    {
        dim3 gg(NB_A, 768 / 64);
        hgemm64<<<gg, 256, 0, s2>>>(x2h_, w3h_, hhA_, 768, 256, 0);
    }
    cudaEventRecord(evG[1], s2);

    // ================= layer 3 =================
    cudaStreamWaitEvent(s1, evF[2], 0);
    alar_wxh<<<cdiv(Nn * 32, 256), 256, 0, s1>>>(x2h_, wl3_, wr3_, al_, ar_, Nn, 12);
    edge_score_csr<12><<<cdiv(Et, 256), 256, 0, s1>>>(csrsrc_, csrdst_, Et, al_, ar_, e_);
    cudaEventRecord(evJ[2], s1);
    cudaStreamWaitEvent(s0, evG[1], 0);
    {
        dim3 gg(NB_TOT - NB_A, 768 / 64);
        hgemm64<<<gg, 256, 0, s0>>>(x2h_, w3h_, hhA_, 768, 256, NB_A);
    }
    cudaStreamWaitEvent(s0, evJ[2], 0);
    agg_h12<<<Nn, 192, 0, s0>>>(rowptr_, csrsrc_, e_, hhA_, b3, x3h_, Nn);

    // ================= fused tail =================
    tail_fused<<<Nn, 128, 0, s0>>>(x1h_, x2h_, x3h_, Wf, bf, px_, M1w,
                                   M2w, M2b, M3w, M3b, out1, out2, Nn);
}

// round 15
// speedup vs baseline: 1.0438x; 1.0438x over previous
#include <cuda_runtime.h>
#include <cuda_fp16.h>
#include <mma.h>
#include <math.h>

using namespace nvcuda;

// ---------------- scratch (device globals; no allocation at launch) ----------------
#define NMAX 10000
#define NP   10048            // NMAX padded to multiple of 64 (guard-free wmma)
#define EMAX 320000
#define ETMAX (EMAX + NMAX)

__device__ __half g_hh [NP * 768];    // GEMM outputs (fp16), padded rows
__device__ __half g_x1h[NP * 256];    // layer outputs, fp16 only
__device__ __half g_x2h[NP * 256];
__device__ __half g_x3h[NP * 768];
__device__ __half g_w2h[256 * 256];   // fp16 weights
__device__ __half g_w3h[256 * 768];
__device__ float g_al [NMAX * 12];
__device__ float g_ar [NMAX * 12];
__device__ float g_e  [12 * ETMAX];   // HEAD-MAJOR: g_e[h*ETMAX + slot] = exp(leaky(score))
__device__ float g_px [NMAX * 128];
__device__ float g_wl1[8 * 16],  g_wr1[8 * 16];     // TRANSPOSED: [h][k]
__device__ float g_wl2[8 * 256], g_wr2[8 * 256];
__device__ float g_wl3[12 * 256], g_wr3[12 * 256];
__device__ int   g_deg   [NMAX];
__device__ int   g_rowptr[NMAX + 1];
__device__ int   g_cursor[NMAX];
__device__ int   g_csrsrc[ETMAX];
__device__ int   g_csrdst[ETMAX];

__device__ __forceinline__ float sigmoidf_(float x) {
    return 1.f / (1.f + expf(-x));
}

static inline int cdiv(int a, int b) { return (a + b - 1) / b; }

// ---------------- CSR build ----------------
__global__ void count_deg(const int* __restrict__ ei, int E, int Et, int* __restrict__ deg) {
    int e = blockIdx.x * blockDim.x + threadIdx.x;
    if (e >= Et) return;
    int d = (e < E) ? ei[E + e] : (e - E);
    atomicAdd(&deg[d], 1);
}

__global__ void scan_deg(const int* __restrict__ deg, int* __restrict__ rowptr,
                         int* __restrict__ cursor, int Nn) {
    __shared__ int part[256];
    __shared__ int partx[256];
    int chunk = (Nn + 255) / 256;
    int begin = threadIdx.x * chunk;
    int end = begin + chunk; if (end > Nn) end = Nn;
    if (begin > Nn) begin = Nn;
    int s = 0;
    for (int i = begin; i < end; ++i) s += deg[i];
    part[threadIdx.x] = s;
    __syncthreads();
    if (threadIdx.x == 0) {
        int run = 0;
        for (int i = 0; i < 256; ++i) { partx[i] = run; run += part[i]; }
    }
    __syncthreads();
    int run = partx[threadIdx.x];
    for (int i = begin; i < end; ++i) {
        rowptr[i] = run; cursor[i] = run;
        run += deg[i];
    }
    if (end == Nn && begin <= Nn) rowptr[Nn] = run;
}

__global__ void scatter_csr(const int* __restrict__ ei, int E, int Et,
                            int* __restrict__ cursor, int* __restrict__ csr_src,
                            int* __restrict__ csr_dst) {
    int e = blockIdx.x * blockDim.x + threadIdx.x;
    if (e >= Et) return;
    int s, d;
    if (e < E) { s = ei[e]; d = ei[E + e]; }
    else       { s = e - E; d = e - E; }
    int pos = atomicAdd(&cursor[d], 1);
    csr_src[pos] = s;
    csr_dst[pos] = d;
}

// ---------------- fold all attention vectors (one launch, TRANSPOSED output) ----------------
__global__ void wa_all(const float* __restrict__ W1, const float* __restrict__ a1s, const float* __restrict__ a1d,
                       const float* __restrict__ W2, const float* __restrict__ a2s, const float* __restrict__ a2d,
                       const float* __restrict__ W3, const float* __restrict__ a3s, const float* __restrict__ a3d,
                       float* __restrict__ wl1, float* __restrict__ wr1,
                       float* __restrict__ wl2, float* __restrict__ wr2,
                       float* __restrict__ wl3, float* __restrict__ wr3) {
    int t = blockIdx.x * blockDim.x + threadIdx.x;
    const float *W, *as, *ad; float *wl, *wr;
    int K, H, C, idx;
    if (t < 128)              { idx = t;        K = 16;  H = 8;  C = 32; W = W1; as = a1s; ad = a1d; wl = wl1; wr = wr1; }
    else if (t < 128 + 2048)  { idx = t - 128;  K = 256; H = 8;  C = 32; W = W2; as = a2s; ad = a2d; wl = wl2; wr = wr2; }
    else if (t < 128 + 2048 + 3072) { idx = t - 2176; K = 256; H = 12; C = 64; W = W3; as = a3s; ad = a3d; wl = wl3; wr = wr3; }
    else return;
    int k = idx / H, h = idx - k * H;
    const float* wrow = W + (size_t)k * H * C + h * C;
    float sl = 0.f, sr = 0.f;
    for (int c = 0; c < C; ++c) {
        float w = wrow[c];
        sl += w * as[h * C + c];
        sr += w * ad[h * C + c];
    }
    wl[h * K + k] = sl;      // transposed
    wr[h * K + k] = sr;
}

// ---------------- fp32 -> fp16 weight conversion (both weights, one launch) ----------------
__global__ void f2h_both(const float* __restrict__ W2, const float* __restrict__ W3,
                         __half* __restrict__ w2h, __half* __restrict__ w3h) {
    int t = blockIdx.x * blockDim.x + threadIdx.x;
    if (t < 256 * 256) w2h[t] = __float2half_rn(W2[t]);
    int u = t - 256 * 256;
    if (u >= 0 && u < 256 * 768) w3h[u] = __float2half_rn(W3[u]);
}

// ---------------- layer-1 SGEMM (K=16, fp32 in, fp16 out) ----------------
__global__ void sgemm64h(const float* __restrict__ A, const float* __restrict__ B,
                         __half* __restrict__ Cmat, int M, int N, int K) {
    __shared__ float As[16][68];
    __shared__ float Bs[16][64];
    int t = threadIdx.x;
    int row0 = blockIdx.x * 64;
    int col0 = blockIdx.y * 64;
    int tx = t & 15, ty = t >> 4;
    int ar = t >> 2, ac = (t & 3) * 4;
    int br = t >> 4, bc = (t & 15) * 4;
    float acc[4][4];
#pragma unroll
    for (int i = 0; i < 4; ++i)
#pragma unroll
        for (int j = 0; j < 4; ++j) acc[i][j] = 0.f;

    for (int k0 = 0; k0 < K; k0 += 16) {
        float4 av = make_float4(0.f, 0.f, 0.f, 0.f);
        if (row0 + ar < M)
            av = *(const float4*)(A + (size_t)(row0 + ar) * K + k0 + ac);
        As[ac + 0][ar] = av.x;
        As[ac + 1][ar] = av.y;
        As[ac + 2][ar] = av.z;
        As[ac + 3][ar] = av.w;
        *(float4*)&Bs[br][bc] = *(const float4*)(B + (size_t)(k0 + br) * N + col0 + bc);
        __syncthreads();
#pragma unroll
        for (int k = 0; k < 16; ++k) {
            float4 a4 = *(const float4*)&As[k][ty * 4];
            float4 b4 = *(const float4*)&Bs[k][tx * 4];
            acc[0][0] += a4.x * b4.x; acc[0][1] += a4.x * b4.y;
            acc[0][2] += a4.x * b4.z; acc[0][3] += a4.x * b4.w;
            acc[1][0] += a4.y * b4.x; acc[1][1] += a4.y * b4.y;
            acc[1][2] += a4.y * b4.z; acc[1][3] += a4.y * b4.w;
            acc[2][0] += a4.z * b4.x; acc[2][1] += a4.z * b4.y;
            acc[2][2] += a4.z * b4.z; acc[2][3] += a4.z * b4.w;
            acc[3][0] += a4.w * b4.x; acc[3][1] += a4.w * b4.y;
            acc[3][2] += a4.w * b4.z; acc[3][3] += a4.w * b4.w;
        }
        __syncthreads();
    }
#pragma unroll
    for (int i = 0; i < 4; ++i) {
        int r = row0 + ty * 4 + i;
        if (r < M) {
            __half2 p0 = __halves2half2(__float2half_rn(acc[i][0]), __float2half_rn(acc[i][1]));
            __half2 p1 = __halves2half2(__float2half_rn(acc[i][2]), __float2half_rn(acc[i][3]));
            __half2* cp = (__half2*)(Cmat + (size_t)r * N + col0 + tx * 4);
            cp[0] = p0;
            cp[1] = p1;
        }
    }
}

// ---------------- HMMA GEMM: C[Mp,N] = A[Mp,K] @ B[K,N], all fp16, fp32 accum ----------------
__global__ void hgemm64(const __half* __restrict__ A, const __half* __restrict__ B,
                        __half* __restrict__ Cmat, int N, int K) {
    __shared__ __half As[64][24];
    __shared__ __half Bs[16][72];
    __shared__ float Cs[8][512];
    int t = threadIdx.x;
    int warp = t >> 5, lane = t & 31;
    int row0 = blockIdx.x * 64, col0 = blockIdx.y * 64;
    int wr = warp & 3;
    int wc = warp >> 2;

    wmma::fragment<wmma::accumulator, 16, 16, 16, float> acc0, acc1;
    wmma::fill_fragment(acc0, 0.f);
    wmma::fill_fragment(acc1, 0.f);

    int arow = t >> 2, acol = (t & 3) * 4;
    int brow = t >> 4, bcol = (t & 15) * 4;

    for (int k0 = 0; k0 < K; k0 += 16) {
        *(uint2*)&As[arow][acol] = *(const uint2*)(A + (size_t)(row0 + arow) * K + k0 + acol);
        *(uint2*)&Bs[brow][bcol] = *(const uint2*)(B + (size_t)(k0 + brow) * N + col0 + bcol);
        __syncthreads();
        wmma::fragment<wmma::matrix_a, 16, 16, 16, __half, wmma::row_major> af;
        wmma::fragment<wmma::matrix_b, 16, 16, 16, __half, wmma::row_major> bf;
        wmma::load_matrix_sync(af, &As[wr * 16][0], 24);
        wmma::load_matrix_sync(bf, &Bs[0][wc * 32], 72);
        wmma::mma_sync(acc0, af, bf, acc0);
        wmma::load_matrix_sync(bf, &Bs[0][wc * 32 + 16], 72);
        wmma::mma_sync(acc1, af, bf, acc1);
        __syncthreads();
    }
    wmma::store_matrix_sync(&Cs[warp][0],  acc0, 32, wmma::mem_row_major);
    wmma::store_matrix_sync(&Cs[warp][16], acc1, 32, wmma::mem_row_major);
    __syncwarp();
    for (int i = lane; i < 512; i += 32) {
        int r = i >> 5, c = i & 31;
        Cmat[(size_t)(row0 + wr * 16 + r) * N + col0 + wc * 32 + c] =
            __float2half_rn(Cs[warp][r * 32 + c]);
    }
}

// ---------------- layer-1 al/ar from fp32 X (transposed w) ----------------
__global__ void alar_x(const float* __restrict__ X,
                       const float* __restrict__ wlt, const float* __restrict__ wrt,
                       float* __restrict__ al, float* __restrict__ ar,
                       int Nn, int K, int H) {
    int t = blockIdx.x * blockDim.x + threadIdx.x;
    if (t >= Nn * H) return;
    int n = t / H, h = t - n * H;
    const float* xr = X + (size_t)n * K;
    const float* wl = wlt + h * K;
    const float* wr = wrt + h * K;
    float sa = 0.f, sd = 0.f;
    for (int k = 0; k < K; ++k) {
        float xv = xr[k];
        sa += xv * wl[k];
        sd += xv * wr[k];
    }
    al[t] = sa;
    ar[t] = sd;
}

// ---------------- layers 2/3 al/ar: warp per node, fp16 X, transposed w (K=256) ----------------
__global__ void alar_wxh(const __half* __restrict__ X,
                         const float* __restrict__ wlt, const float* __restrict__ wrt,
                         float* __restrict__ al, float* __restrict__ ar,
                         int Nn, int H) {
    const int K = 256;
    int gw = (blockIdx.x * blockDim.x + threadIdx.x) >> 5;
    int lane = threadIdx.x & 31;
    if (gw >= Nn) return;
    float xv[8];
    const __half2* xr = (const __half2*)(X + (size_t)gw * K) + lane * 4;
#pragma unroll
    for (int i = 0; i < 4; ++i) {
        float2 f = __half22float2(xr[i]);
        xv[2 * i] = f.x; xv[2 * i + 1] = f.y;
    }
    for (int h = 0; h < H; ++h) {
        const float4* wl4 = (const float4*)(wlt + h * K + lane * 8);
        const float4* wr4 = (const float4*)(wrt + h * K + lane * 8);
        float4 la = wl4[0], lb = wl4[1];
        float4 ra = wr4[0], rb = wr4[1];
        float sa = xv[0]*la.x + xv[1]*la.y + xv[2]*la.z + xv[3]*la.w
                 + xv[4]*lb.x + xv[5]*lb.y + xv[6]*lb.z + xv[7]*lb.w;
        float sd = xv[0]*ra.x + xv[1]*ra.y + xv[2]*ra.z + xv[3]*ra.w
                 + xv[4]*rb.x + xv[5]*rb.y + xv[6]*rb.z + xv[7]*rb.w;
#pragma unroll
        for (int o = 16; o; o >>= 1) {
            sa += __shfl_xor_sync(0xffffffffu, sa, o);
            sd += __shfl_xor_sync(0xffffffffu, sd, o);
        }
        if (lane == 0) {
            al[gw * H + h] = sa;
            ar[gw * H + h] = sd;
        }
    }
}

// ---------------- per-slot exp(leaky(score)) (CSR order, HEAD-MAJOR) ----------------
template<int H>
__global__ void edge_score_csr(const int* __restrict__ csr_src, const int* __restrict__ csr_dst,
                               int Et,
                               const float* __restrict__ al, const float* __restrict__ ar,
                               float* __restrict__ ebuf) {
    int i = blockIdx.x * blockDim.x + threadIdx.x;
    if (i >= Et) return;
    int s = csr_src[i];
    int d = csr_dst[i];
    const float4* a4 = (const float4*)(al + s * H);
    const float4* r4 = (const float4*)(ar + d * H);
#pragma unroll
    for (int q = 0; q < H / 4; ++q) {
        float4 a = a4[q], r = r4[q];
        float v0 = a.x + r.x; v0 = v0 > 0.f ? v0 : 0.2f * v0;
        float v1 = a.y + r.y; v1 = v1 > 0.f ? v1 : 0.2f * v1;
        float v2 = a.z + r.z; v2 = v2 > 0.f ? v2 : 0.2f * v2;
        float v3 = a.w + r.w; v3 = v3 > 0.f ? v3 : 0.2f * v3;
        ebuf[(size_t)(q * 4 + 0) * ETMAX + i] = __expf(v0);
        ebuf[(size_t)(q * 4 + 1) * ETMAX + i] = __expf(v1);
        ebuf[(size_t)(q * 4 + 2) * ETMAX + i] = __expf(v2);
        ebuf[(size_t)(q * 4 + 3) * ETMAX + i] = __expf(v3);
    }
}

// ---------------- agg (H=8, C=32): 4 warps, 2 heads/warp, fp16-only output ----------------
__global__ void agg_h8(const int* __restrict__ rowptr, const int* __restrict__ csr_src,
                       const float* __restrict__ ebuf, const __half* __restrict__ Hmat,
                       const float* __restrict__ bias, __half* __restrict__ Outh, int Nn) {
    __shared__ int ssrc[128];
    int n = blockIdx.x;
    int t = threadIdx.x;
    int w = t >> 5, lane = t & 31;
    int rs = rowptr[n], re = rowptr[n + 1];
    const float* ep0 = ebuf + (size_t)(2 * w)     * ETMAX;
    const float* ep1 = ebuf + (size_t)(2 * w + 1) * ETMAX;
    bool hi = lane >= 16;

    float ssum = 0.f, acc0 = 0.f, acc1 = 0.f;
    for (int base = rs; base < re; base += 128) {
        int cnt = re - base; if (cnt > 128) cnt = 128;
        __syncthreads();
        if (t < cnt) ssrc[t] = csr_src[base + t];
        __syncthreads();
#pragma unroll 4
        for (int j = 0; j < cnt; ++j) {
            int s = ssrc[j];
            float a = hi ? ep1[base + j] : ep0[base + j];
            ssum += a;
            const __half2* hp = (const __half2*)(Hmat + (size_t)s * 256 + w * 64);
            float2 vf = __half22float2(hp[lane]);
            acc0 += a * vf.x;
            acc1 += a * vf.y;
        }
    }
    float inv_s = 1.f / ssum;
    int c = w * 64 + lane * 2;
    float v0 = acc0 * inv_s + bias[c];
    float v1 = acc1 * inv_s + bias[c + 1];
    v0 = v0 > 0.f ? v0 : 0.f;
    v1 = v1 > 0.f ? v1 : 0.f;
    *((__half2*)(Outh + (size_t)n * 256 + c)) = __floats2half2_rn(v0, v1);
}

// ---------------- agg (H=12, C=64): 6 warps, 2 heads/warp, uint2 gathers ----------------
__global__ void agg_h12(const int* __restrict__ rowptr, const int* __restrict__ csr_src,
                        const float* __restrict__ ebuf, const __half* __restrict__ Hmat,
                        const float* __restrict__ bias, __half* __restrict__ Outh, int Nn) {
    __shared__ int ssrc[192];
    int n = blockIdx.x;
    int t = threadIdx.x;
    int w = t >> 5, lane = t & 31;
    int rs = rowptr[n], re = rowptr[n + 1];
    const float* ep0 = ebuf + (size_t)(2 * w)     * ETMAX;
    const float* ep1 = ebuf + (size_t)(2 * w + 1) * ETMAX;
    bool hi = lane >= 16;

    float ssum = 0.f, acc0 = 0.f, acc1 = 0.f, acc2 = 0.f, acc3 = 0.f;
    for (int base = rs; base < re; base += 192) {
        int cnt = re - base; if (cnt > 192) cnt = 192;
        __syncthreads();
        if (t < cnt) ssrc[t] = csr_src[base + t];
        __syncthreads();
#pragma unroll 4
        for (int j = 0; j < cnt; ++j) {
            int s = ssrc[j];
            float a = hi ? ep1[base + j] : ep0[base + j];
            ssum += a;
            const uint2* hp = (const uint2*)(Hmat + (size_t)s * 768 + w * 128);
            uint2 u = hp[lane];
            float2 f01 = __half22float2(*(__half2*)&u.x);
            float2 f23 = __half22float2(*(__half2*)&u.y);
            acc0 += a * f01.x;
            acc1 += a * f01.y;
            acc2 += a * f23.x;
            acc3 += a * f23.y;
        }
    }
    float inv_s = 1.f / ssum;
    int c = w * 128 + lane * 4;
    float v0 = acc0 * inv_s + bias[c];
    float v1 = acc1 * inv_s + bias[c + 1];
    float v2 = acc2 * inv_s + bias[c + 2];
    float v3 = acc3 * inv_s + bias[c + 3];
    v0 = v0 > 0.f ? v0 : 0.f;
    v1 = v1 > 0.f ? v1 : 0.f;
    v2 = v2 > 0.f ? v2 : 0.f;
    v3 = v3 > 0.f ? v3 : 0.f;
    __half2* op = (__half2*)(Outh + (size_t)n * 768 + c);
    op[0] = __floats2half2_rn(v0, v1);
    op[1] = __floats2half2_rn(v2, v3);
}

// ---------------- fused tail (fp16 activations in) ----------------
__global__ void tail_fused(const __half* __restrict__ x1, const __half* __restrict__ x2,
                           const __half* __restrict__ x3, const float* __restrict__ Wf,
                           const float* __restrict__ bf, const float* __restrict__ px,
                           const float* __restrict__ M1w,
                           const float* __restrict__ M2w, const float* __restrict__ M2b,
                           const float* __restrict__ M3w, const float* __restrict__ M3b,
                           float* __restrict__ out1, float* __restrict__ out2, int Nn) {
    __shared__ float red[4];
    __shared__ float h1s[128];
    __shared__ float h2s[64];
    __shared__ float o1s;
    int n = blockIdx.x;
    int t = threadIdx.x;
    int lane = t & 31, w = t >> 5;

    float acc = 0.f;
    const __half* p1 = x1 + (size_t)n * 256;
    const __half* p2 = x2 + (size_t)n * 256;
    const __half* p3 = x3 + (size_t)n * 768;
    for (int j = t; j < 256; j += 128) acc += __half2float(p1[j]) * Wf[j];
    for (int j = t; j < 256; j += 128) acc += __half2float(p2[j]) * Wf[256 + j];
    for (int j = t; j < 768; j += 128) acc += __half2float(p3[j]) * Wf[512 + j];
#pragma unroll
    for (int o = 16; o; o >>= 1) acc += __shfl_xor_sync(0xffffffffu, acc, o);
    if (lane == 0) red[w] = acc;
    __syncthreads();
    if (t == 0) {
        float s = red[0] + red[1] + red[2] + red[3];
        float o1 = sigmoidf_(s + bf[0]);
        o1s = o1;
        out1[n] = o1;
    }
    __syncthreads();
    float o1 = o1s;

    float hv = px[(size_t)n * 128 + t] + o1 * M1w[16 * 128 + t];
    h1s[t] = hv > 0.f ? hv : 0.f;
    __syncthreads();

    if (t < 64) {
        float a = M2b[t];
#pragma unroll 8
        for (int k = 0; k < 128; ++k) a += h1s[k] * M2w[k * 64 + t];
        h2s[t] = a > 0.f ? a : 0.f;
    }
    __syncthreads();

    if (w == 0) {
        float a = h2s[lane] * M3w[lane] + h2s[lane + 32] * M3w[lane + 32];
#pragma unroll
        for (int o = 16; o; o >>= 1) a += __shfl_down_sync(0xffffffffu, a, o);
        if (lane == 0) out2[n] = sigmoidf_(a + M3b[0]);
    }
}

// ---------------- mlp1 x-part precompute (overlapped) ----------------
__global__ void mlp1_pre(const float* __restrict__ x,
                         const float* __restrict__ M1w, const float* __restrict__ M1b,
                         float* __restrict__ px, int Nn) {
    int t = blockIdx.x * blockDim.x + threadIdx.x;
    if (t >= Nn * 128) return;
    int n = t / 128, j = t - n * 128;
    float acc = M1b[j];
    const float* xr = x + n * 16;
#pragma unroll
    for (int k = 0; k < 16; ++k) acc += xr[k] * M1w[k * 128 + j];
    px[t] = acc;
}

extern "C" void kernel_launch(void* const* d_in, const int* in_sizes, int n_in,
                              void* d_out, int out_size) {
    const float* x   = (const float*)d_in[0];
    const int*   ei  = (const int*)  d_in[1];
    const float* W1  = (const float*)d_in[3];
    const float* a1s = (const float*)d_in[4];
    const float* a1d = (const float*)d_in[5];
    const float* b1  = (const float*)d_in[6];
    const float* W2  = (const float*)d_in[7];
    const float* a2s = (const float*)d_in[8];
    const float* a2d = (const float*)d_in[9];
    const float* b2  = (const float*)d_in[10];
    const float* W3  = (const float*)d_in[11];
    const float* a3s = (const float*)d_in[12];
    const float* a3d = (const float*)d_in[13];
    const float* b3  = (const float*)d_in[14];
    const float* Wf  = (const float*)d_in[15];
    const float* bf  = (const float*)d_in[16];
    const float* M1w = (const float*)d_in[17];
    const float* M1b = (const float*)d_in[18];
    const float* M2w = (const float*)d_in[19];
    const float* M2b = (const float*)d_in[20];
    const float* M3w = (const float*)d_in[21];
    const float* M3b = (const float*)d_in[22];

    int Nn = in_sizes[0] / 16;
    int E  = in_sizes[1] / 2;
    int Et = E + Nn;

    __half *hh_, *x1h_, *x2h_, *x3h_, *w2h_, *w3h_;
    float *al_, *ar_, *e_, *px_;
    float *wl1_, *wr1_, *wl2_, *wr2_, *wl3_, *wr3_;
    int *deg_, *rowptr_, *cursor_, *csrsrc_, *csrdst_;
    cudaGetSymbolAddress((void**)&hh_,    g_hh);
    cudaGetSymbolAddress((void**)&x1h_,   g_x1h);
    cudaGetSymbolAddress((void**)&x2h_,   g_x2h);
    cudaGetSymbolAddress((void**)&x3h_,   g_x3h);
    cudaGetSymbolAddress((void**)&w2h_,   g_w2h);
    cudaGetSymbolAddress((void**)&w3h_,   g_w3h);
    cudaGetSymbolAddress((void**)&al_,    g_al);
    cudaGetSymbolAddress((void**)&ar_,    g_ar);
    cudaGetSymbolAddress((void**)&e_,     g_e);
    cudaGetSymbolAddress((void**)&px_,    g_px);
    cudaGetSymbolAddress((void**)&wl1_,   g_wl1);
    cudaGetSymbolAddress((void**)&wr1_,   g_wr1);
    cudaGetSymbolAddress((void**)&wl2_,   g_wl2);
    cudaGetSymbolAddress((void**)&wr2_,   g_wr2);
    cudaGetSymbolAddress((void**)&wl3_,   g_wl3);
    cudaGetSymbolAddress((void**)&wr3_,   g_wr3);
    cudaGetSymbolAddress((void**)&deg_,   g_deg);
    cudaGetSymbolAddress((void**)&rowptr_,g_rowptr);
    cudaGetSymbolAddress((void**)&cursor_,g_cursor);
    cudaGetSymbolAddress((void**)&csrsrc_,g_csrsrc);
    cudaGetSymbolAddress((void**)&csrdst_,g_csrdst);

    float* out1 = (float*)d_out;
    float* out2 = (float*)d_out + Nn;

    static cudaStream_t s1 = nullptr;
    static cudaEvent_t evF[3], evJ[3], evW;
    if (!s1) {
        cudaStreamCreateWithFlags(&s1, cudaStreamNonBlocking);
        for (int i = 0; i < 3; ++i) {
            cudaEventCreateWithFlags(&evF[i], cudaEventDisableTiming);
            cudaEventCreateWithFlags(&evJ[i], cudaEventDisableTiming);
        }
        cudaEventCreateWithFlags(&evW, cudaEventDisableTiming);
    }
    cudaStream_t s0 = 0;

    // ================= layer 1: fork =================
    cudaEventRecord(evF[0], s0);
    cudaStreamWaitEvent(s1, evF[0], 0);
    // side chain: weight prep + CSR + layer-1 scores + mlp1 precompute
    wa_all<<<cdiv(5248, 128), 128, 0, s1>>>(W1, a1s, a1d, W2, a2s, a2d, W3, a3s, a3d,
                                            wl1_, wr1_, wl2_, wr2_, wl3_, wr3_);
    cudaMemsetAsync(deg_, 0, Nn * sizeof(int), s1);
    count_deg<<<cdiv(Et, 256), 256, 0, s1>>>(ei, E, Et, deg_);
    scan_deg<<<1, 256, 0, s1>>>(deg_, rowptr_, cursor_, Nn);
    scatter_csr<<<cdiv(Et, 256), 256, 0, s1>>>(ei, E, Et, cursor_, csrsrc_, csrdst_);
    alar_x<<<cdiv(Nn * 8, 256), 256, 0, s1>>>(x, wl1_, wr1_, al_, ar_, Nn, 16, 8);
    edge_score_csr<8><<<cdiv(Et, 256), 256, 0, s1>>>(csrsrc_, csrdst_, Et, al_, ar_, e_);
    mlp1_pre<<<cdiv(Nn * 128, 256), 256, 0, s1>>>(x, M1w, M1b, px_, Nn);
    cudaEventRecord(evJ[0], s1);
    f2h_both<<<cdiv(256 * 1024, 256), 256, 0, s1>>>(W2, W3, w2h_, w3h_);
    cudaEventRecord(evW, s1);
    // main: GEMM1 (fp32 in, K=16)
    {
        dim3 gg(cdiv(Nn, 64), 256 / 64);
        sgemm64h<<<gg, 256, 0, s0>>>(x, W1, hh_, Nn, 256, 16);
    }
    cudaStreamWaitEvent(s0, evJ[0], 0);
    agg_h8<<<Nn, 128, 0, s0>>>(rowptr_, csrsrc_, e_, hh_, b1, x1h_, Nn);

    // ================= layer 2 =================
    cudaEventRecord(evF[1], s0);
    cudaStreamWaitEvent(s1, evF[1], 0);
    alar_wxh<<<cdiv(Nn * 32, 256), 256, 0, s1>>>(x1h_, wl2_, wr2_, al_, ar_, Nn, 8);
    edge_score_csr<8><<<cdiv(Et, 256), 256, 0, s1>>>(csrsrc_, csrdst_, Et, al_, ar_, e_);
    cudaEventRecord(evJ[1], s1);
    cudaStreamWaitEvent(s0, evW, 0);
    {
        dim3 gg(NP / 64, 256 / 64);
        hgemm64<<<gg, 256, 0, s0>>>(x1h_, w2h_, hh_, 256, 256);
    }
    cudaStreamWaitEvent(s0, evJ[1], 0);
    agg_h8<<<Nn, 128, 0, s0>>>(rowptr_, csrsrc_, e_, hh_, b2, x2h_, Nn);

    // ================= layer 3 =================
    cudaEventRecord(evF[2], s0);
    cudaStreamWaitEvent(s1, evF[2], 0);
    alar_wxh<<<cdiv(Nn * 32, 256), 256, 0, s1>>>(x2h_, wl3_, wr3_, al_, ar_, Nn, 12);
    edge_score_csr<12><<<cdiv(Et, 256), 256, 0, s1>>>(csrsrc_, csrdst_, Et, al_, ar_, e_);
    cudaEventRecord(evJ[2], s1);
    {
        dim3 gg(NP / 64, 768 / 64);
        hgemm64<<<gg, 256, 0, s0>>>(x2h_, w3h_, hh_, 768, 256);
    }
    cudaStreamWaitEvent(s0, evJ[2], 0);
    agg_h12<<<Nn, 192, 0, s0>>>(rowptr_, csrsrc_, e_, hh_, b3, x3h_, Nn);

    // ================= fused tail =================
    tail_fused<<<Nn, 128, 0, s0>>>(x1h_, x2h_, x3h_, Wf, bf, px_, M1w,
                                   M2w, M2b, M3w, M3b, out1, out2, Nn);
}

// round 16
// speedup vs baseline: 1.0521x; 1.0079x over previous
#include <cuda_runtime.h>
#include <cuda_fp16.h>
#include <mma.h>
#include <math.h>

using namespace nvcuda;

// ---------------- scratch (device globals; no allocation at launch) ----------------
#define NMAX 10000
#define NP   10048            // NMAX padded to multiple of 64 (guard-free wmma)
#define EMAX 320000
#define ETMAX (EMAX + NMAX)

__device__ __half g_hh [NP * 768];    // GEMM outputs (fp16), padded rows
__device__ __half g_x1h[NP * 256];    // layer outputs, fp16 only
__device__ __half g_x2h[NP * 256];
__device__ __half g_x3h[NP * 768];
__device__ __half g_w2h[256 * 256];   // fp16 weights
__device__ __half g_w3h[256 * 768];
__device__ float g_al [NMAX * 12];
__device__ float g_ar [NMAX * 12];
__device__ float g_e  [(size_t)ETMAX * 12];   // EDGE-MAJOR: g_e[slot*H + h] = exp(leaky(score))
__device__ float g_px [NMAX * 128];
__device__ float g_wl1[8 * 16],  g_wr1[8 * 16];     // TRANSPOSED: [h][k]
__device__ float g_wl2[8 * 256], g_wr2[8 * 256];
__device__ float g_wl3[12 * 256], g_wr3[12 * 256];
__device__ int   g_deg   [NMAX];
__device__ int   g_rowptr[NMAX + 1];
__device__ int   g_cursor[NMAX];
__device__ int   g_csrsrc[ETMAX];
__device__ int   g_csrdst[ETMAX];

__device__ __forceinline__ float sigmoidf_(float x) {
    return 1.f / (1.f + expf(-x));
}

static inline int cdiv(int a, int b) { return (a + b - 1) / b; }

// ---------------- CSR build ----------------
__global__ void count_deg(const int* __restrict__ ei, int E, int Et, int* __restrict__ deg) {
    int e = blockIdx.x * blockDim.x + threadIdx.x;
    if (e >= Et) return;
    int d = (e < E) ? ei[E + e] : (e - E);
    atomicAdd(&deg[d], 1);
}

__global__ void scan_deg(const int* __restrict__ deg, int* __restrict__ rowptr,
                         int* __restrict__ cursor, int Nn) {
    __shared__ int part[256];
    __shared__ int partx[256];
    int chunk = (Nn + 255) / 256;
    int begin = threadIdx.x * chunk;
    int end = begin + chunk; if (end > Nn) end = Nn;
    if (begin > Nn) begin = Nn;
    int s = 0;
    for (int i = begin; i < end; ++i) s += deg[i];
    part[threadIdx.x] = s;
    __syncthreads();
    if (threadIdx.x == 0) {
        int run = 0;
        for (int i = 0; i < 256; ++i) { partx[i] = run; run += part[i]; }
    }
    __syncthreads();
    int run = partx[threadIdx.x];
    for (int i = begin; i < end; ++i) {
        rowptr[i] = run; cursor[i] = run;
        run += deg[i];
    }
    if (end == Nn && begin <= Nn) rowptr[Nn] = run;
}

// fused scatter + layer-1 scores (H=8, edge-major exp scores)
__global__ void scatter_score8(const int* __restrict__ ei, int E, int Et,
                               int* __restrict__ cursor, int* __restrict__ csr_src,
                               int* __restrict__ csr_dst,
                               const float* __restrict__ al, const float* __restrict__ ar,
                               float* __restrict__ ebuf) {
    int e = blockIdx.x * blockDim.x + threadIdx.x;
    if (e >= Et) return;
    int s, d;
    if (e < E) { s = ei[e]; d = ei[E + e]; }
    else       { s = e - E; d = e - E; }
    int pos = atomicAdd(&cursor[d], 1);
    csr_src[pos] = s;
    csr_dst[pos] = d;
    const float4* a4 = (const float4*)(al + s * 8);
    const float4* r4 = (const float4*)(ar + d * 8);
    float4* o4 = (float4*)(ebuf + (size_t)pos * 8);
#pragma unroll
    for (int q = 0; q < 2; ++q) {
        float4 a = a4[q], r = r4[q];
        float v0 = a.x + r.x; v0 = v0 > 0.f ? v0 : 0.2f * v0;
        float v1 = a.y + r.y; v1 = v1 > 0.f ? v1 : 0.2f * v1;
        float v2 = a.z + r.z; v2 = v2 > 0.f ? v2 : 0.2f * v2;
        float v3 = a.w + r.w; v3 = v3 > 0.f ? v3 : 0.2f * v3;
        o4[q] = make_float4(__expf(v0), __expf(v1), __expf(v2), __expf(v3));
    }
}

// ---------------- fold all attention vectors (one launch, TRANSPOSED output) ----------------
__global__ void wa_all(const float* __restrict__ W1, const float* __restrict__ a1s, const float* __restrict__ a1d,
                       const float* __restrict__ W2, const float* __restrict__ a2s, const float* __restrict__ a2d,
                       const float* __restrict__ W3, const float* __restrict__ a3s, const float* __restrict__ a3d,
                       float* __restrict__ wl1, float* __restrict__ wr1,
                       float* __restrict__ wl2, float* __restrict__ wr2,
                       float* __restrict__ wl3, float* __restrict__ wr3) {
    int t = blockIdx.x * blockDim.x + threadIdx.x;
    const float *W, *as, *ad; float *wl, *wr;
    int K, H, C, idx;
    if (t < 128)              { idx = t;        K = 16;  H = 8;  C = 32; W = W1; as = a1s; ad = a1d; wl = wl1; wr = wr1; }
    else if (t < 128 + 2048)  { idx = t - 128;  K = 256; H = 8;  C = 32; W = W2; as = a2s; ad = a2d; wl = wl2; wr = wr2; }
    else if (t < 128 + 2048 + 3072) { idx = t - 2176; K = 256; H = 12; C = 64; W = W3; as = a3s; ad = a3d; wl = wl3; wr = wr3; }
    else return;
    int k = idx / H, h = idx - k * H;
    const float* wrow = W + (size_t)k * H * C + h * C;
    float sl = 0.f, sr = 0.f;
    for (int c = 0; c < C; ++c) {
        float w = wrow[c];
        sl += w * as[h * C + c];
        sr += w * ad[h * C + c];
    }
    wl[h * K + k] = sl;      // transposed
    wr[h * K + k] = sr;
}

// ---------------- fp32 -> fp16 weight conversion (both weights, one launch) ----------------
__global__ void f2h_both(const float* __restrict__ W2, const float* __restrict__ W3,
                         __half* __restrict__ w2h, __half* __restrict__ w3h) {
    int t = blockIdx.x * blockDim.x + threadIdx.x;
    if (t < 256 * 256) w2h[t] = __float2half_rn(W2[t]);
    int u = t - 256 * 256;
    if (u >= 0 && u < 256 * 768) w3h[u] = __float2half_rn(W3[u]);
}

// ---------------- layer-1 SGEMM (K=16, fp32 in, fp16 out) ----------------
__global__ void sgemm64h(const float* __restrict__ A, const float* __restrict__ B,
                         __half* __restrict__ Cmat, int M, int N, int K) {
    __shared__ float As[16][68];
    __shared__ float Bs[16][64];
    int t = threadIdx.x;
    int row0 = blockIdx.x * 64;
    int col0 = blockIdx.y * 64;
    int tx = t & 15, ty = t >> 4;
    int ar = t >> 2, ac = (t & 3) * 4;
    int br = t >> 4, bc = (t & 15) * 4;
    float acc[4][4];
#pragma unroll
    for (int i = 0; i < 4; ++i)
#pragma unroll
        for (int j = 0; j < 4; ++j) acc[i][j] = 0.f;

    for (int k0 = 0; k0 < K; k0 += 16) {
        float4 av = make_float4(0.f, 0.f, 0.f, 0.f);
        if (row0 + ar < M)
            av = *(const float4*)(A + (size_t)(row0 + ar) * K + k0 + ac);
        As[ac + 0][ar] = av.x;
        As[ac + 1][ar] = av.y;
        As[ac + 2][ar] = av.z;
        As[ac + 3][ar] = av.w;
        *(float4*)&Bs[br][bc] = *(const float4*)(B + (size_t)(k0 + br) * N + col0 + bc);
        __syncthreads();
#pragma unroll
        for (int k = 0; k < 16; ++k) {
            float4 a4 = *(const float4*)&As[k][ty * 4];
            float4 b4 = *(const float4*)&Bs[k][tx * 4];
            acc[0][0] += a4.x * b4.x; acc[0][1] += a4.x * b4.y;
            acc[0][2] += a4.x * b4.z; acc[0][3] += a4.x * b4.w;
            acc[1][0] += a4.y * b4.x; acc[1][1] += a4.y * b4.y;
            acc[1][2] += a4.y * b4.z; acc[1][3] += a4.y * b4.w;
            acc[2][0] += a4.z * b4.x; acc[2][1] += a4.z * b4.y;
            acc[2][2] += a4.z * b4.z; acc[2][3] += a4.z * b4.w;
            acc[3][0] += a4.w * b4.x; acc[3][1] += a4.w * b4.y;
            acc[3][2] += a4.w * b4.z; acc[3][3] += a4.w * b4.w;
        }
        __syncthreads();
    }
#pragma unroll
    for (int i = 0; i < 4; ++i) {
        int r = row0 + ty * 4 + i;
        if (r < M) {
            __half2 p0 = __halves2half2(__float2half_rn(acc[i][0]), __float2half_rn(acc[i][1]));
            __half2 p1 = __halves2half2(__float2half_rn(acc[i][2]), __float2half_rn(acc[i][3]));
            __half2* cp = (__half2*)(Cmat + (size_t)r * N + col0 + tx * 4);
            cp[0] = p0;
            cp[1] = p1;
        }
    }
}

// ---------------- HMMA GEMM: C[Mp,N] = A[Mp,K] @ B[K,N], all fp16, fp32 accum ----------------
__global__ void hgemm64(const __half* __restrict__ A, const __half* __restrict__ B,
                        __half* __restrict__ Cmat, int N, int K) {
    __shared__ __half As[64][24];
    __shared__ __half Bs[16][72];
    __shared__ float Cs[8][512];
    int t = threadIdx.x;
    int warp = t >> 5, lane = t & 31;
    int row0 = blockIdx.x * 64, col0 = blockIdx.y * 64;
    int wr = warp & 3;
    int wc = warp >> 2;

    wmma::fragment<wmma::accumulator, 16, 16, 16, float> acc0, acc1;
    wmma::fill_fragment(acc0, 0.f);
    wmma::fill_fragment(acc1, 0.f);

    int arow = t >> 2, acol = (t & 3) * 4;
    int brow = t >> 4, bcol = (t & 15) * 4;

    for (int k0 = 0; k0 < K; k0 += 16) {
        *(uint2*)&As[arow][acol] = *(const uint2*)(A + (size_t)(row0 + arow) * K + k0 + acol);
        *(uint2*)&Bs[brow][bcol] = *(const uint2*)(B + (size_t)(k0 + brow) * N + col0 + bcol);
        __syncthreads();
        wmma::fragment<wmma::matrix_a, 16, 16, 16, __half, wmma::row_major> af;
        wmma::fragment<wmma::matrix_b, 16, 16, 16, __half, wmma::row_major> bf;
        wmma::load_matrix_sync(af, &As[wr * 16][0], 24);
        wmma::load_matrix_sync(bf, &Bs[0][wc * 32], 72);
        wmma::mma_sync(acc0, af, bf, acc0);
        wmma::load_matrix_sync(bf, &Bs[0][wc * 32 + 16], 72);
        wmma::mma_sync(acc1, af, bf, acc1);
        __syncthreads();
    }
    wmma::store_matrix_sync(&Cs[warp][0],  acc0, 32, wmma::mem_row_major);
    wmma::store_matrix_sync(&Cs[warp][16], acc1, 32, wmma::mem_row_major);
    __syncwarp();
    for (int i = lane; i < 512; i += 32) {
        int r = i >> 5, c = i & 31;
        Cmat[(size_t)(row0 + wr * 16 + r) * N + col0 + wc * 32 + c] =
            __float2half_rn(Cs[warp][r * 32 + c]);
    }
}

// ---------------- layer-1 al/ar from fp32 X (transposed w) ----------------
__global__ void alar_x(const float* __restrict__ X,
                       const float* __restrict__ wlt, const float* __restrict__ wrt,
                       float* __restrict__ al, float* __restrict__ ar,
                       int Nn, int K, int H) {
    int t = blockIdx.x * blockDim.x + threadIdx.x;
    if (t >= Nn * H) return;
    int n = t / H, h = t - n * H;
    const float* xr = X + (size_t)n * K;
    const float* wl = wlt + h * K;
    const float* wr = wrt + h * K;
    float sa = 0.f, sd = 0.f;
    for (int k = 0; k < K; ++k) {
        float xv = xr[k];
        sa += xv * wl[k];
        sd += xv * wr[k];
    }
    al[t] = sa;
    ar[t] = sd;
}

// ---------------- layers 2/3 al/ar: warp per node, fp16 X, transposed w (K=256) ----------------
__global__ void alar_wxh(const __half* __restrict__ X,
                         const float* __restrict__ wlt, const float* __restrict__ wrt,
                         float* __restrict__ al, float* __restrict__ ar,
                         int Nn, int H) {
    const int K = 256;
    int gw = (blockIdx.x * blockDim.x + threadIdx.x) >> 5;
    int lane = threadIdx.x & 31;
    if (gw >= Nn) return;
    float xv[8];
    const __half2* xr = (const __half2*)(X + (size_t)gw * K) + lane * 4;
#pragma unroll
    for (int i = 0; i < 4; ++i) {
        float2 f = __half22float2(xr[i]);
        xv[2 * i] = f.x; xv[2 * i + 1] = f.y;
    }
    for (int h = 0; h < H; ++h) {
        const float4* wl4 = (const float4*)(wlt + h * K + lane * 8);
        const float4* wr4 = (const float4*)(wrt + h * K + lane * 8);
        float4 la = wl4[0], lb = wl4[1];
        float4 ra = wr4[0], rb = wr4[1];
        float sa = xv[0]*la.x + xv[1]*la.y + xv[2]*la.z + xv[3]*la.w
                 + xv[4]*lb.x + xv[5]*lb.y + xv[6]*lb.z + xv[7]*lb.w;
        float sd = xv[0]*ra.x + xv[1]*ra.y + xv[2]*ra.z + xv[3]*ra.w
                 + xv[4]*rb.x + xv[5]*rb.y + xv[6]*rb.z + xv[7]*rb.w;
#pragma unroll
        for (int o = 16; o; o >>= 1) {
            sa += __shfl_xor_sync(0xffffffffu, sa, o);
            sd += __shfl_xor_sync(0xffffffffu, sd, o);
        }
        if (lane == 0) {
            al[gw * H + h] = sa;
            ar[gw * H + h] = sd;
        }
    }
}

// ---------------- per-slot exp(leaky(score)) (CSR order, EDGE-MAJOR) ----------------
template<int H>
__global__ void edge_score_csr(const int* __restrict__ csr_src, const int* __restrict__ csr_dst,
                               int Et,
                               const float* __restrict__ al, const float* __restrict__ ar,
                               float* __restrict__ ebuf) {
    int i = blockIdx.x * blockDim.x + threadIdx.x;
    if (i >= Et) return;
    int s = csr_src[i];
    int d = csr_dst[i];
    const float4* a4 = (const float4*)(al + s * H);
    const float4* r4 = (const float4*)(ar + d * H);
    float4* o4 = (float4*)(ebuf + (size_t)i * H);
#pragma unroll
    for (int q = 0; q < H / 4; ++q) {
        float4 a = a4[q], r = r4[q];
        float v0 = a.x + r.x; v0 = v0 > 0.f ? v0 : 0.2f * v0;
        float v1 = a.y + r.y; v1 = v1 > 0.f ? v1 : 0.2f * v1;
        float v2 = a.z + r.z; v2 = v2 > 0.f ? v2 : 0.2f * v2;
        float v3 = a.w + r.w; v3 = v3 > 0.f ? v3 : 0.2f * v3;
        o4[q] = make_float4(__expf(v0), __expf(v1), __expf(v2), __expf(v3));
    }
}

// ---------------- agg (H=8, C=32): 4 warps, 2 heads/warp; scores staged in smem ----------------
__global__ void agg_h8(const int* __restrict__ rowptr, const int* __restrict__ csr_src,
                       const float* __restrict__ ebuf, const __half* __restrict__ Hmat,
                       const float* __restrict__ bias, __half* __restrict__ Outh, int Nn) {
    __shared__ int ssrc[128];
    __shared__ float esc[8][128];
    int n = blockIdx.x;
    int t = threadIdx.x;
    int w = t >> 5, lane = t & 31;
    int rs = rowptr[n], re = rowptr[n + 1];
    bool hi = lane >= 16;
    int h0 = 2 * w, h1 = 2 * w + 1;

    float ssum = 0.f, acc0 = 0.f, acc1 = 0.f;
    for (int base = rs; base < re; base += 128) {
        int cnt = re - base; if (cnt > 128) cnt = 128;
        __syncthreads();
        if (t < cnt) {
            ssrc[t] = csr_src[base + t];
            const float4* e4 = (const float4*)(ebuf + (size_t)(base + t) * 8);
            float4 q0 = e4[0], q1 = e4[1];
            esc[0][t] = q0.x; esc[1][t] = q0.y; esc[2][t] = q0.z; esc[3][t] = q0.w;
            esc[4][t] = q1.x; esc[5][t] = q1.y; esc[6][t] = q1.z; esc[7][t] = q1.w;
        }
        __syncthreads();
#pragma unroll 4
        for (int j = 0; j < cnt; ++j) {
            int s = ssrc[j];
            float a = hi ? esc[h1][j] : esc[h0][j];
            ssum += a;
            const __half2* hp = (const __half2*)(Hmat + (size_t)s * 256 + w * 64);
            float2 vf = __half22float2(hp[lane]);
            acc0 += a * vf.x;
            acc1 += a * vf.y;
        }
    }
    float inv_s = 1.f / ssum;
    int c = w * 64 + lane * 2;
    float v0 = acc0 * inv_s + bias[c];
    float v1 = acc1 * inv_s + bias[c + 1];
    v0 = v0 > 0.f ? v0 : 0.f;
    v1 = v1 > 0.f ? v1 : 0.f;
    *((__half2*)(Outh + (size_t)n * 256 + c)) = __floats2half2_rn(v0, v1);
}

// ---------------- agg (H=12, C=64): 6 warps, 2 heads/warp; scores staged in smem ----------------
__global__ void agg_h12(const int* __restrict__ rowptr, const int* __restrict__ csr_src,
                        const float* __restrict__ ebuf, const __half* __restrict__ Hmat,
                        const float* __restrict__ bias, __half* __restrict__ Outh, int Nn) {
    __shared__ int ssrc[192];
    __shared__ float esc[12][192];
    int n = blockIdx.x;
    int t = threadIdx.x;            // 192 threads
    int w = t >> 5, lane = t & 31;
    int rs = rowptr[n], re = rowptr[n + 1];
    bool hi = lane >= 16;
    int h0 = 2 * w, h1 = 2 * w + 1;

    float ssum = 0.f, acc0 = 0.f, acc1 = 0.f, acc2 = 0.f, acc3 = 0.f;
    for (int base = rs; base < re; base += 192) {
        int cnt = re - base; if (cnt > 192) cnt = 192;
        __syncthreads();
        if (t < cnt) {
            ssrc[t] = csr_src[base + t];
            const float4* e4 = (const float4*)(ebuf + (size_t)(base + t) * 12);
            float4 q0 = e4[0], q1 = e4[1], q2 = e4[2];
            esc[0][t] = q0.x; esc[1][t]  = q0.y; esc[2][t]  = q0.z; esc[3][t]  = q0.w;
            esc[4][t] = q1.x; esc[5][t]  = q1.y; esc[6][t]  = q1.z; esc[7][t]  = q1.w;
            esc[8][t] = q2.x; esc[9][t]  = q2.y; esc[10][t] = q2.z; esc[11][t] = q2.w;
        }
        __syncthreads();
#pragma unroll 4
        for (int j = 0; j < cnt; ++j) {
            int s = ssrc[j];
            float a = hi ? esc[h1][j] : esc[h0][j];
            ssum += a;
            const uint2* hp = (const uint2*)(Hmat + (size_t)s * 768 + w * 128);
            uint2 u = hp[lane];
            float2 f01 = __half22float2(*(__half2*)&u.x);
            float2 f23 = __half22float2(*(__half2*)&u.y);
            acc0 += a * f01.x;
            acc1 += a * f01.y;
            acc2 += a * f23.x;
            acc3 += a * f23.y;
        }
    }
    float inv_s = 1.f / ssum;
    int c = w * 128 + lane * 4;
    float v0 = acc0 * inv_s + bias[c];
    float v1 = acc1 * inv_s + bias[c + 1];
    float v2 = acc2 * inv_s + bias[c + 2];
    float v3 = acc3 * inv_s + bias[c + 3];
    v0 = v0 > 0.f ? v0 : 0.f;
    v1 = v1 > 0.f ? v1 : 0.f;
    v2 = v2 > 0.f ? v2 : 0.f;
    v3 = v3 > 0.f ? v3 : 0.f;
    __half2* op = (__half2*)(Outh + (size_t)n * 768 + c);
    op[0] = __floats2half2_rn(v0, v1);
    op[1] = __floats2half2_rn(v2, v3);
}

// ---------------- fused tail (fp16 activations in) ----------------
__global__ void tail_fused(const __half* __restrict__ x1, const __half* __restrict__ x2,
                           const __half* __restrict__ x3, const float* __restrict__ Wf,
                           const float* __restrict__ bf, const float* __restrict__ px,
                           const float* __restrict__ M1w,
                           const float* __restrict__ M2w, const float* __restrict__ M2b,
                           const float* __restrict__ M3w, const float* __restrict__ M3b,
                           float* __restrict__ out1, float* __restrict__ out2, int Nn) {
    __shared__ float red[4];
    __shared__ float h1s[128];
    __shared__ float h2s[64];
    __shared__ float o1s;
    int n = blockIdx.x;
    int t = threadIdx.x;
    int lane = t & 31, w = t >> 5;

    float acc = 0.f;
    const __half* p1 = x1 + (size_t)n * 256;
    const __half* p2 = x2 + (size_t)n * 256;
    const __half* p3 = x3 + (size_t)n * 768;
    for (int j = t; j < 256; j += 128) acc += __half2float(p1[j]) * Wf[j];
    for (int j = t; j < 256; j += 128) acc += __half2float(p2[j]) * Wf[256 + j];
    for (int j = t; j < 768; j += 128) acc += __half2float(p3[j]) * Wf[512 + j];
#pragma unroll
    for (int o = 16; o; o >>= 1) acc += __shfl_xor_sync(0xffffffffu, acc, o);
    if (lane == 0) red[w] = acc;
    __syncthreads();
    if (t == 0) {
        float s = red[0] + red[1] + red[2] + red[3];
        float o1 = sigmoidf_(s + bf[0]);
        o1s = o1;
        out1[n] = o1;
    }
    __syncthreads();
    float o1 = o1s;

    float hv = px[(size_t)n * 128 + t] + o1 * M1w[16 * 128 + t];
    h1s[t] = hv > 0.f ? hv : 0.f;
    __syncthreads();

    if (t < 64) {
        float a = M2b[t];
#pragma unroll 8
        for (int k = 0; k < 128; ++k) a += h1s[k] * M2w[k * 64 + t];
        h2s[t] = a > 0.f ? a : 0.f;
    }
    __syncthreads();

    if (w == 0) {
        float a = h2s[lane] * M3w[lane] + h2s[lane + 32] * M3w[lane + 32];
#pragma unroll
        for (int o = 16; o; o >>= 1) a += __shfl_down_sync(0xffffffffu, a, o);
        if (lane == 0) out2[n] = sigmoidf_(a + M3b[0]);
    }
}

// ---------------- mlp1 x-part precompute (overlapped) ----------------
__global__ void mlp1_pre(const float* __restrict__ x,
                         const float* __restrict__ M1w, const float* __restrict__ M1b,
                         float* __restrict__ px, int Nn) {
    int t = blockIdx.x * blockDim.x + threadIdx.x;
    if (t >= Nn * 128) return;
    int n = t / 128, j = t - n * 128;
    float acc = M1b[j];
    const float* xr = x + n * 16;
#pragma unroll
    for (int k = 0; k < 16; ++k) acc += xr[k] * M1w[k * 128 + j];
    px[t] = acc;
}

extern "C" void kernel_launch(void* const* d_in, const int* in_sizes, int n_in,
                              void* d_out, int out_size) {
    const float* x   = (const float*)d_in[0];
    const int*   ei  = (const int*)  d_in[1];
    const float* W1  = (const float*)d_in[3];
    const float* a1s = (const float*)d_in[4];
    const float* a1d = (const float*)d_in[5];
    const float* b1  = (const float*)d_in[6];
    const float* W2  = (const float*)d_in[7];
    const float* a2s = (const float*)d_in[8];
    const float* a2d = (const float*)d_in[9];
    const float* b2  = (const float*)d_in[10];
    const float* W3  = (const float*)d_in[11];
    const float* a3s = (const float*)d_in[12];
    const float* a3d = (const float*)d_in[13];
    const float* b3  = (const float*)d_in[14];
    const float* Wf  = (const float*)d_in[15];
    const float* bf  = (const float*)d_in[16];
    const float* M1w = (const float*)d_in[17];
    const float* M1b = (const float*)d_in[18];
    const float* M2w = (const float*)d_in[19];
    const float* M2b = (const float*)d_in[20];
    const float* M3w = (const float*)d_in[21];
    const float* M3b = (const float*)d_in[22];

    int Nn = in_sizes[0] / 16;
    int E  = in_sizes[1] / 2;
    int Et = E + Nn;

    __half *hh_, *x1h_, *x2h_, *x3h_, *w2h_, *w3h_;
    float *al_, *ar_, *e_, *px_;
    float *wl1_, *wr1_, *wl2_, *wr2_, *wl3_, *wr3_;
    int *deg_, *rowptr_, *cursor_, *csrsrc_, *csrdst_;
    cudaGetSymbolAddress((void**)&hh_,    g_hh);
    cudaGetSymbolAddress((void**)&x1h_,   g_x1h);
    cudaGetSymbolAddress((void**)&x2h_,   g_x2h);
    cudaGetSymbolAddress((void**)&x3h_,   g_x3h);
    cudaGetSymbolAddress((void**)&w2h_,   g_w2h);
    cudaGetSymbolAddress((void**)&w3h_,   g_w3h);
    cudaGetSymbolAddress((void**)&al_,    g_al);
    cudaGetSymbolAddress((void**)&ar_,    g_ar);
    cudaGetSymbolAddress((void**)&e_,     g_e);
    cudaGetSymbolAddress((void**)&px_,    g_px);
    cudaGetSymbolAddress((void**)&wl1_,   g_wl1);
    cudaGetSymbolAddress((void**)&wr1_,   g_wr1);
    cudaGetSymbolAddress((void**)&wl2_,   g_wl2);
    cudaGetSymbolAddress((void**)&wr2_,   g_wr2);
    cudaGetSymbolAddress((void**)&wl3_,   g_wl3);
    cudaGetSymbolAddress((void**)&wr3_,   g_wr3);
    cudaGetSymbolAddress((void**)&deg_,   g_deg);
    cudaGetSymbolAddress((void**)&rowptr_,g_rowptr);
    cudaGetSymbolAddress((void**)&cursor_,g_cursor);
    cudaGetSymbolAddress((void**)&csrsrc_,g_csrsrc);
    cudaGetSymbolAddress((void**)&csrdst_,g_csrdst);

    float* out1 = (float*)d_out;
    float* out2 = (float*)d_out + Nn;

    static cudaStream_t s1 = nullptr, s2 = nullptr;
    static cudaEvent_t evF0, evF[3], evJ[3], evW, evAL, evPX;
    if (!s1) {
        cudaStreamCreateWithFlags(&s1, cudaStreamNonBlocking);
        cudaStreamCreateWithFlags(&s2, cudaStreamNonBlocking);
        cudaEventCreateWithFlags(&evF0, cudaEventDisableTiming);
        for (int i = 0; i < 3; ++i) {
            cudaEventCreateWithFlags(&evF[i], cudaEventDisableTiming);
            cudaEventCreateWithFlags(&evJ[i], cudaEventDisableTiming);
        }
        cudaEventCreateWithFlags(&evW, cudaEventDisableTiming);
        cudaEventCreateWithFlags(&evAL, cudaEventDisableTiming);
        cudaEventCreateWithFlags(&evPX, cudaEventDisableTiming);
    }
    cudaStream_t s0 = 0;

    // ================= layer 1: fork =================
    cudaEventRecord(evF0, s0);
    cudaStreamWaitEvent(s1, evF0, 0);
    cudaStreamWaitEvent(s2, evF0, 0);
    // s2: weight fold + layer-1 al/ar + mlp1 precompute
    wa_all<<<cdiv(5248, 128), 128, 0, s2>>>(W1, a1s, a1d, W2, a2s, a2d, W3, a3s, a3d,
                                            wl1_, wr1_, wl2_, wr2_, wl3_, wr3_);
    alar_x<<<cdiv(Nn * 8, 256), 256, 0, s2>>>(x, wl1_, wr1_, al_, ar_, Nn, 16, 8);
    cudaEventRecord(evAL, s2);
    mlp1_pre<<<cdiv(Nn * 128, 256), 256, 0, s2>>>(x, M1w, M1b, px_, Nn);
    cudaEventRecord(evPX, s2);
    // s1: CSR chain, then fused scatter+score (needs al/ar)
    cudaMemsetAsync(deg_, 0, Nn * sizeof(int), s1);
    count_deg<<<cdiv(Et, 256), 256, 0, s1>>>(ei, E, Et, deg_);
    scan_deg<<<1, 256, 0, s1>>>(deg_, rowptr_, cursor_, Nn);
    cudaStreamWaitEvent(s1, evAL, 0);
    scatter_score8<<<cdiv(Et, 256), 256, 0, s1>>>(ei, E, Et, cursor_, csrsrc_, csrdst_,
                                                  al_, ar_, e_);
    cudaEventRecord(evJ[0], s1);
    f2h_both<<<cdiv(256 * 1024, 256), 256, 0, s1>>>(W2, W3, w2h_, w3h_);
    cudaEventRecord(evW, s1);
    // s0: GEMM1 (fp32 in, K=16)
    {
        dim3 gg(cdiv(Nn, 64), 256 / 64);
        sgemm64h<<<gg, 256, 0, s0>>>(x, W1, hh_, Nn, 256, 16);
    }
    cudaStreamWaitEvent(s0, evJ[0], 0);
    agg_h8<<<Nn, 128, 0, s0>>>(rowptr_, csrsrc_, e_, hh_, b1, x1h_, Nn);

    // ================= layer 2 =================
    cudaEventRecord(evF[1], s0);
    cudaStreamWaitEvent(s1, evF[1], 0);
    alar_wxh<<<cdiv(Nn * 32, 256), 256, 0, s1>>>(x1h_, wl2_, wr2_, al_, ar_, Nn, 8);
    edge_score_csr<8><<<cdiv(Et, 256), 256, 0, s1>>>(csrsrc_, csrdst_, Et, al_, ar_, e_);
    cudaEventRecord(evJ[1], s1);
    cudaStreamWaitEvent(s0, evW, 0);
    {
        dim3 gg(NP / 64, 256 / 64);
        hgemm64<<<gg, 256, 0, s0>>>(x1h_, w2h_, hh_, 256, 256);
    }
    cudaStreamWaitEvent(s0, evJ[1], 0);
    agg_h8<<<Nn, 128, 0, s0>>>(rowptr_, csrsrc_, e_, hh_, b2, x2h_, Nn);

    // ================= layer 3 =================
    cudaEventRecord(evF[2], s0);
    cudaStreamWaitEvent(s1, evF[2], 0);
    alar_wxh<<<cdiv(Nn * 32, 256), 256, 0, s1>>>(x2h_, wl3_, wr3_, al_, ar_, Nn, 12);
    edge_score_csr<12><<<cdiv(Et, 256), 256, 0, s1>>>(csrsrc_, csrdst_, Et, al_, ar_, e_);
    cudaEventRecord(evJ[2], s1);
    {
        dim3 gg(NP / 64, 768 / 64);
        hgemm64<<<gg, 256, 0, s0>>>(x2h_, w3h_, hh_, 768, 256);
    }
    cudaStreamWaitEvent(s0, evJ[2], 0);
    agg_h12<<<Nn, 192, 0, s0>>>(rowptr_, csrsrc_, e_, hh_, b3, x3h_, Nn);

    // ================= fused tail =================
    cudaStreamWaitEvent(s0, evPX, 0);
    tail_fused<<<Nn, 128, 0, s0>>>(x1h_, x2h_, x3h_, Wf, bf, px_, M1w,
                                   M2w, M2b, M3w, M3b, out1, out2, Nn);
}